// round 1
// baseline (speedup 1.0000x reference)
#include <cuda_runtime.h>
#include <cstdint>

// Problem constants (fixed by the reference):
//   B=1024, FANOUTS=[10,25], DIM=256, N_NODES=100000
#define DIM   256
#define HALFD 128

// Scratch (device globals; allocation-free per harness rules)
__device__ float g_n1[10240 * DIM];  // layer0 output on hop-1 nodes
__device__ float g_n0[1024  * DIM];  // layer0 output on hop-0 nodes

// ---- packed f32x2 helpers (ptxas won't auto-fuse FFMA2; must use PTX) ----
__device__ __forceinline__ unsigned long long pack2(float a, float b) {
    unsigned long long r;
    asm("mov.b64 %0, {%1, %2};" : "=l"(r) : "f"(a), "f"(b));
    return r;
}
__device__ __forceinline__ unsigned long long ffma2(
    unsigned long long a, unsigned long long b, unsigned long long c) {
    unsigned long long d;
    asm("fma.rn.f32x2 %0, %1, %2, %3;" : "=l"(d) : "l"(a), "l"(b), "l"(c));
    return d;
}

// One "half layer": for rows [m0, m0+TM):
//   X[r] = mean_{j<F} src[idx[row*F + j]]        (idx==nullptr -> contiguous)
//   out[row, col_off + c] = (ReLU?)( X[r] . W[:, c] )   for c in [0,128)
// F==1 is exactly the "self" path (mean over one row == gather).
template <int TM, int F, bool RELU>
__global__ void __launch_bounds__(256)
sage_half_kernel(const float* __restrict__ src,
                 const int*   __restrict__ idx,
                 const float* __restrict__ W,     // [256,128] row-major
                 float*       __restrict__ out,   // [nrows,256]
                 int col_off)
{
    __shared__ float X[TM * DIM];
    const int tid = threadIdx.x;
    const int m0  = blockIdx.x * TM;

    // ---- gather + mean: 256 threads cover one row's 256 cols per step ----
    #pragma unroll 1
    for (int r = 0; r < TM; ++r) {
        const long base = (long)(m0 + r) * F;
        float acc = 0.0f;
        #pragma unroll
        for (int j = 0; j < F; ++j) {
            const int g = idx ? idx[base + j] : (int)(base + j);
            acc += src[(size_t)g * DIM + tid];
        }
        X[r * DIM + tid] = acc * (1.0f / (float)F);
    }
    __syncthreads();

    // ---- GEMM: thread -> (column c, row-half). 2 threads share a column. ----
    const int c  = tid & (HALFD - 1);
    const int r0 = (tid >> 7) * (TM / 2);
    const float* __restrict__ Wc = W + c;

    unsigned long long acc2[TM / 2];
    #pragma unroll
    for (int r = 0; r < TM / 2; ++r) acc2[r] = 0ull;  // bits of (0.f,0.f)

    #pragma unroll 2
    for (int k0 = 0; k0 < DIM; k0 += 4) {
        const unsigned long long wp0 = pack2(Wc[(k0 + 0) * HALFD], Wc[(k0 + 1) * HALFD]);
        const unsigned long long wp1 = pack2(Wc[(k0 + 2) * HALFD], Wc[(k0 + 3) * HALFD]);
        #pragma unroll
        for (int r = 0; r < TM / 2; ++r) {
            const ulonglong2 xv =
                *reinterpret_cast<const ulonglong2*>(&X[(r0 + r) * DIM + k0]);
            acc2[r] = ffma2(xv.x, wp0, acc2[r]);
            acc2[r] = ffma2(xv.y, wp1, acc2[r]);
        }
    }

    #pragma unroll
    for (int r = 0; r < TM / 2; ++r) {
        const float lo = __uint_as_float((unsigned)(acc2[r] & 0xffffffffull));
        const float hi = __uint_as_float((unsigned)(acc2[r] >> 32));
        float v = lo + hi;
        if (RELU) v = fmaxf(v, 0.0f);
        out[(size_t)(m0 + r0 + r) * DIM + col_off + c] = v;
    }
}

extern "C" void kernel_launch(void* const* d_in, const int* in_sizes, int n_in,
                              void* d_out, int out_size)
{
    const float* features = (const float*)d_in[0];
    const int*   sn0      = (const int*)  d_in[1];
    const int*   sn1      = (const int*)  d_in[2];
    const int*   sn2      = (const int*)  d_in[3];
    const float* W0s      = (const float*)d_in[4];
    const float* W0n      = (const float*)d_in[5];
    const float* W1s      = (const float*)d_in[6];
    const float* W1n      = (const float*)d_in[7];
    float*       out      = (float*)      d_out;

    float* n1 = nullptr;
    float* n0 = nullptr;
    cudaGetSymbolAddress((void**)&n1, g_n1);
    cudaGetSymbolAddress((void**)&n0, g_n0);

    // layer 0 on hop-1 nodes -> n1 [10240,256]   (bulk of the work)
    sage_half_kernel<32, 1,  true ><<<320, 256>>>(features, sn1, W0s, n1, 0);
    sage_half_kernel<32, 25, true ><<<320, 256>>>(features, sn2, W0n, n1, HALFD);

    // layer 0 on hop-0 nodes -> n0 [1024,256]
    sage_half_kernel<8, 1,  true ><<<128, 256>>>(features, sn0, W0s, n0, 0);
    sage_half_kernel<8, 10, true ><<<128, 256>>>(features, sn1, W0n, n0, HALFD);

    // layer 1 (no activation) -> out [1024,256]
    sage_half_kernel<8, 1,  false><<<128, 256>>>(n0, nullptr, W1s, out, 0);
    sage_half_kernel<8, 10, false><<<128, 256>>>(n1, nullptr, W1n, out, HALFD);
}

// round 2
// speedup vs baseline: 1.6169x; 1.6169x over previous
#include <cuda_runtime.h>
#include <cstdint>

// Problem constants: B=1024, FANOUTS=[10,25], DIM=256, N_NODES=100000
#define DIM   256
#define D4    64      // DIM / 4
#define HALF  128

// Scratch (device globals; allocation-free per harness rules)
__device__ float g_n1[10240 * DIM];  // layer0 output on hop-1 nodes
__device__ float g_n0[1024  * DIM];  // layer0 output on hop-0 nodes

typedef unsigned long long u64;

// ---- packed f32x2 helpers (ptxas won't auto-fuse FFMA2; must use PTX) ----
__device__ __forceinline__ u64 pack2(float a, float b) {
    u64 r;
    asm("mov.b64 %0, {%1, %2};" : "=l"(r) : "f"(a), "f"(b));
    return r;
}
__device__ __forceinline__ u64 ffma2(u64 a, u64 b, u64 c) {
    u64 d;
    asm("fma.rn.f32x2 %0, %1, %2, %3;" : "=l"(d) : "l"(a), "l"(b), "l"(c));
    return d;
}

// One fused tile: TM rows.
//   Xs[r] = ssrc[ sidx?sidx[row]:row ]                  (self)
//   Xn[r] = mean_{j<F} nsrc[ nidx?nidx[row*F+j]:row*F+j ]  (neigh)
//   out[row][0:128]   = act( Xs[r] @ Ws )
//   out[row][128:256] = act( Xn[r] @ Wn )
template <int TM, int F, bool RELU, bool SIDX, bool NIDX>
__device__ __forceinline__ void sage_tile(
    const float4* __restrict__ ssrc4,
    const float4* __restrict__ nsrc4,
    const int*    __restrict__ sidx,
    const int*    __restrict__ nidx,
    const float*  __restrict__ Ws,   // [256,128] row-major
    const float*  __restrict__ Wn,   // [256,128] row-major
    float*        __restrict__ out,  // [nrows,256]
    int m0,
    float4* Xs4, float4* Xn4)
{
    const int tid = threadIdx.x;  // 512 threads

    // ---- gather + mean: one (row, float4-slot) per thread, F-way MLP ----
    #pragma unroll
    for (int i = tid; i < TM * D4; i += 512) {
        const int r   = i >> 6;
        const int q   = i & 63;
        const int row = m0 + r;

        // self
        const int gs = SIDX ? sidx[row] : row;
        Xs4[i] = ssrc4[(size_t)gs * D4 + q];

        // neigh (mean over F)
        float4 a = make_float4(0.f, 0.f, 0.f, 0.f);
        const size_t nb = (size_t)row * F;
        #pragma unroll
        for (int j = 0; j < F; ++j) {
            const int g = NIDX ? nidx[nb + j] : (int)(nb + j);
            const float4 v = nsrc4[(size_t)g * D4 + q];
            a.x += v.x; a.y += v.y; a.z += v.z; a.w += v.w;
        }
        const float inv = 1.0f / (float)F;
        a.x *= inv; a.y *= inv; a.z *= inv; a.w *= inv;
        Xn4[i] = a;
    }
    __syncthreads();

    // ---- GEMM: thread -> (output column c in [0,256), row-half rh) ----
    const float* Xs = reinterpret_cast<const float*>(Xs4);
    const float* Xn = reinterpret_cast<const float*>(Xn4);
    const int c  = tid & 255;
    const int rh = tid >> 8;                  // 0 or 1
    const bool self_half = (c < HALF);        // warp-uniform
    const float* __restrict__ X  = self_half ? Xs : Xn;
    const float* __restrict__ Wc = (self_half ? Ws : Wn) + (c & (HALF - 1));

    constexpr int RPT = TM / 2;
    const int r0 = rh * RPT;

    u64 acc[RPT];
    #pragma unroll
    for (int r = 0; r < RPT; ++r) acc[r] = 0ull;   // bits of (0.f, 0.f)

    #pragma unroll 2
    for (int k0 = 0; k0 < DIM; k0 += 4) {
        const u64 w01 = pack2(__ldg(Wc + (k0 + 0) * HALF), __ldg(Wc + (k0 + 1) * HALF));
        const u64 w23 = pack2(__ldg(Wc + (k0 + 2) * HALF), __ldg(Wc + (k0 + 3) * HALF));
        #pragma unroll
        for (int r = 0; r < RPT; ++r) {
            const ulonglong2 xv =
                *reinterpret_cast<const ulonglong2*>(&X[(r0 + r) * DIM + k0]);
            acc[r] = ffma2(xv.x, w01, acc[r]);
            acc[r] = ffma2(xv.y, w23, acc[r]);
        }
    }

    #pragma unroll
    for (int r = 0; r < RPT; ++r) {
        const float lo = __uint_as_float((unsigned)(acc[r] & 0xffffffffull));
        const float hi = __uint_as_float((unsigned)(acc[r] >> 32));
        float v = lo + hi;
        if (RELU) v = fmaxf(v, 0.0f);
        out[(size_t)(m0 + r0 + r) * DIM + c] = v;
    }
}

// K1: layer 0 for both n1 (10240 rows, F=25) and n0 (1024 rows, F=10).
// blocks [0,640): n1 tiles; blocks [640,704): n0 tiles. TM=16.
__global__ void __launch_bounds__(512)
sage_layer0_kernel(const float4* __restrict__ feat4,
                   const int* __restrict__ sn0,
                   const int* __restrict__ sn1,
                   const int* __restrict__ sn2,
                   const float* __restrict__ W0s,
                   const float* __restrict__ W0n,
                   float* __restrict__ n1,
                   float* __restrict__ n0)
{
    __shared__ float4 Xs4[16 * D4];
    __shared__ float4 Xn4[16 * D4];
    if (blockIdx.x < 640) {
        sage_tile<16, 25, true, true, true>(
            feat4, feat4, sn1, sn2, W0s, W0n, n1, blockIdx.x * 16, Xs4, Xn4);
    } else {
        sage_tile<16, 10, true, true, true>(
            feat4, feat4, sn0, sn1, W0s, W0n, n0, (blockIdx.x - 640) * 16, Xs4, Xn4);
    }
}

// K2: layer 1 (no activation). self = n0 rows (identity), neigh = mean10 of
// contiguous n1 rows. TM=8 -> 128 CTAs.
__global__ void __launch_bounds__(512)
sage_layer1_kernel(const float4* __restrict__ n0_4,
                   const float4* __restrict__ n1_4,
                   const float* __restrict__ W1s,
                   const float* __restrict__ W1n,
                   float* __restrict__ out)
{
    __shared__ float4 Xs4[8 * D4];
    __shared__ float4 Xn4[8 * D4];
    sage_tile<8, 10, false, false, false>(
        n0_4, n1_4, nullptr, nullptr, W1s, W1n, out, blockIdx.x * 8, Xs4, Xn4);
}

extern "C" void kernel_launch(void* const* d_in, const int* in_sizes, int n_in,
                              void* d_out, int out_size)
{
    const float4* feat4 = (const float4*)d_in[0];
    const int*    sn0   = (const int*)  d_in[1];
    const int*    sn1   = (const int*)  d_in[2];
    const int*    sn2   = (const int*)  d_in[3];
    const float*  W0s   = (const float*)d_in[4];
    const float*  W0n   = (const float*)d_in[5];
    const float*  W1s   = (const float*)d_in[6];
    const float*  W1n   = (const float*)d_in[7];
    float*        out   = (float*)      d_out;

    float* n1 = nullptr;
    float* n0 = nullptr;
    cudaGetSymbolAddress((void**)&n1, g_n1);
    cudaGetSymbolAddress((void**)&n0, g_n0);

    sage_layer0_kernel<<<704, 512>>>(feat4, sn0, sn1, sn2, W0s, W0n, n1, n0);
    sage_layer1_kernel<<<128, 512>>>((const float4*)n0, (const float4*)n1,
                                     W1s, W1n, out);
}

// round 3
// speedup vs baseline: 2.1164x; 1.3089x over previous
#include <cuda_runtime.h>
#include <cstdint>

// Problem constants: B=1024, FANOUTS=[10,25], DIM=256, N_NODES=100000
#define DIM   256
#define D4    64      // DIM / 4
#define HALF  128

typedef unsigned long long u64;

// Scratch (device globals; allocation-free per harness rules)
__device__ float g_n1[10240 * DIM];  // layer0 output on hop-1 nodes
__device__ float g_n0[1024  * DIM];  // layer0 output on hop-0 nodes

// ---- packed f32x2 helpers (ptxas won't auto-fuse FFMA2; must use PTX) ----
__device__ __forceinline__ u64 pack2(float a, float b) {
    u64 r;
    asm("mov.b64 %0, {%1, %2};" : "=l"(r) : "f"(a), "f"(b));
    return r;
}
__device__ __forceinline__ u64 ffma2(u64 a, u64 b, u64 c) {
    u64 d;
    asm("fma.rn.f32x2 %0, %1, %2, %3;" : "=l"(d) : "l"(a), "l"(b), "l"(c));
    return d;
}

// One fused tile of TM rows:
//   Xs[r] = ssrc[ sidx? sidx[row] : row ]
//   Xn[r] = mean_{j<F} nsrc[ nidx? nidx[row*F+j] : row*F+j ]
//   out[row][0:128]   = act( Xs[r] @ Ws )
//   out[row][128:256] = act( Xn[r] @ Wn )
template <int TM, int F, int THREADS, bool RELU, bool SIDX, bool NIDX>
__device__ __forceinline__ void sage_tile(
    const float4* __restrict__ ssrc4,
    const float4* __restrict__ nsrc4,
    const int*    __restrict__ sidx,
    const int*    __restrict__ nidx,
    const float*  __restrict__ Ws,   // [256,128] row-major
    const float*  __restrict__ Wn,   // [256,128] row-major
    float*        __restrict__ out,  // [nrows,256]
    int m0,
    float4* Xs4, float4* Xn4)
{
    const int tid = threadIdx.x;
    constexpr int ITEMS = TM * D4;

    // ---- gather + mean: one (row, float4-slot) per thread per step ----
    #pragma unroll
    for (int it = 0; it < (ITEMS + THREADS - 1) / THREADS; ++it) {
        const int i = it * THREADS + tid;
        if ((ITEMS % THREADS) != 0 && i >= ITEMS) break;
        const int r   = i >> 6;
        const int q   = i & 63;
        const int row = m0 + r;

        const int gs = SIDX ? sidx[row] : row;           // warp-uniform idx load
        Xs4[i] = ssrc4[(size_t)gs * D4 + q];

        float4 a = make_float4(0.f, 0.f, 0.f, 0.f);
        const size_t nb = (size_t)row * F;
        #pragma unroll
        for (int j = 0; j < F; ++j) {
            const int g = NIDX ? nidx[nb + j] : (int)(nb + j);
            const float4 v = nsrc4[(size_t)g * D4 + q];
            a.x += v.x; a.y += v.y; a.z += v.z; a.w += v.w;
        }
        const float inv = 1.0f / (float)F;
        a.x *= inv; a.y *= inv; a.z *= inv; a.w *= inv;
        Xn4[i] = a;
    }
    __syncthreads();

    // ---- GEMM: thread -> (output column c in [0,256), row-group) ----
    constexpr int RQ  = THREADS / 256;   // row groups
    constexpr int RPT = TM / RQ;         // rows per thread
    const int c  = tid & 255;
    const int r0 = (tid >> 8) * RPT;
    const bool self_half = (c < HALF);   // warp-uniform
    const float* __restrict__ X  =
        reinterpret_cast<const float*>(self_half ? Xs4 : Xn4);
    const float* __restrict__ Wc = (self_half ? Ws : Wn) + (c & (HALF - 1));

    u64 acc[RPT];
    #pragma unroll
    for (int r = 0; r < RPT; ++r) acc[r] = 0ull;  // bits of (0.f, 0.f)

    #pragma unroll 4
    for (int k0 = 0; k0 < DIM; k0 += 4) {
        const u64 w01 = pack2(__ldg(Wc + (k0 + 0) * HALF), __ldg(Wc + (k0 + 1) * HALF));
        const u64 w23 = pack2(__ldg(Wc + (k0 + 2) * HALF), __ldg(Wc + (k0 + 3) * HALF));
        #pragma unroll
        for (int r = 0; r < RPT; ++r) {
            // warp-uniform smem address -> broadcast, conflict-free
            const ulonglong2 xv =
                *reinterpret_cast<const ulonglong2*>(&X[(r0 + r) * DIM + k0]);
            acc[r] = ffma2(xv.x, w01, acc[r]);
            acc[r] = ffma2(xv.y, w23, acc[r]);
        }
    }

    #pragma unroll
    for (int r = 0; r < RPT; ++r) {
        const float lo = __uint_as_float((unsigned)(acc[r] & 0xffffffffull));
        const float hi = __uint_as_float((unsigned)(acc[r] >> 32));
        float v = lo + hi;
        if (RELU) v = fmaxf(v, 0.0f);
        out[(size_t)(m0 + r0 + r) * DIM + c] = v;
    }
}

// K1: layer 0. blocks [0,320): n1 (10240 rows, F=25); [320,352): n0 (1024, F=10).
// TM=32, 1024 threads, 64KB dynamic smem.
extern __shared__ float4 smem_dyn[];

__global__ void __launch_bounds__(1024, 1)
sage_layer0_kernel(const float4* __restrict__ feat4,
                   const int* __restrict__ sn0,
                   const int* __restrict__ sn1,
                   const int* __restrict__ sn2,
                   const float* __restrict__ W0s,
                   const float* __restrict__ W0n,
                   float* __restrict__ n1,
                   float* __restrict__ n0)
{
    float4* Xs4 = smem_dyn;
    float4* Xn4 = smem_dyn + 32 * D4;
    if (blockIdx.x < 320) {
        sage_tile<32, 25, 1024, true, true, true>(
            feat4, feat4, sn1, sn2, W0s, W0n, n1, blockIdx.x * 32, Xs4, Xn4);
    } else {
        sage_tile<32, 10, 1024, true, true, true>(
            feat4, feat4, sn0, sn1, W0s, W0n, n0, (blockIdx.x - 320) * 32, Xs4, Xn4);
    }
}

// K2: layer 1 (no activation). self = n0 rows (identity), neigh = mean10 of
// contiguous n1 rows. TM=4 -> 256 CTAs (beats the old 1-wave grid limit).
__global__ void __launch_bounds__(512)
sage_layer1_kernel(const float4* __restrict__ n0_4,
                   const float4* __restrict__ n1_4,
                   const float* __restrict__ W1s,
                   const float* __restrict__ W1n,
                   float* __restrict__ out)
{
    __shared__ float4 Xs4[4 * D4];
    __shared__ float4 Xn4[4 * D4];
    sage_tile<4, 10, 512, false, false, false>(
        n0_4, n1_4, nullptr, nullptr, W1s, W1n, out, blockIdx.x * 4, Xs4, Xn4);
}

extern "C" void kernel_launch(void* const* d_in, const int* in_sizes, int n_in,
                              void* d_out, int out_size)
{
    const float4* feat4 = (const float4*)d_in[0];
    const int*    sn0   = (const int*)  d_in[1];
    const int*    sn1   = (const int*)  d_in[2];
    const int*    sn2   = (const int*)  d_in[3];
    const float*  W0s   = (const float*)d_in[4];
    const float*  W0n   = (const float*)d_in[5];
    const float*  W1s   = (const float*)d_in[6];
    const float*  W1n   = (const float*)d_in[7];
    float*        out   = (float*)      d_out;

    float* n1 = nullptr;
    float* n0 = nullptr;
    cudaGetSymbolAddress((void**)&n1, g_n1);
    cudaGetSymbolAddress((void**)&n0, g_n0);

    static bool attr_set = false;
    if (!attr_set) {
        cudaFuncSetAttribute(sage_layer0_kernel,
                             cudaFuncAttributeMaxDynamicSharedMemorySize,
                             64 * 1024);
        attr_set = true;
    }

    sage_layer0_kernel<<<352, 1024, 64 * 1024>>>(
        feat4, sn0, sn1, sn2, W0s, W0n, n1, n0);
    sage_layer1_kernel<<<256, 512>>>(
        (const float4*)n0, (const float4*)n1, W1s, W1n, out);
}